// round 7
// baseline (speedup 1.0000x reference)
#include <cuda_runtime.h>
#include <cuda_bf16.h>

#define BB 8
#define LL 200
#define HH 128
#define NHH 4
#define DHH 32
#define SCALE 0.17677669529663688f   // 1/sqrt(32)

__device__ float g_Q[BB * LL * HH];
__device__ float g_K[BB * LL * HH];
__device__ float g_V[BB * LL * HH];
__device__ float g_S[BB * NHH * LL * LL];   // base scores Qs.(K+pK)

// ---------------------------------------------------------------------------
// Projection: grid (50 row-tiles, 3 matrices) = 150 CTAs (~one wave),
// 256 threads. W transposed in-CTA during staging (no separate kernel).
// ---------------------------------------------------------------------------
__global__ __launch_bounds__(256) void proj_kernel(
    const float* __restrict__ queries, const float* __restrict__ keys,
    const float* __restrict__ apK, const float* __restrict__ apV,
    const float* __restrict__ Qw, const float* __restrict__ Kw,
    const float* __restrict__ Vw,
    const float* __restrict__ Qb, const float* __restrict__ Kb,
    const float* __restrict__ Vb)
{
    __shared__ float sXT[HH * 36];        // [k][row(+pad)]
    __shared__ float sW[2][32 * 129];     // [k][col(+pad)]

    const int tid = threadIdx.x;
    const int col = tid & 127;
    const int rg  = tid >> 7;
    const int g   = blockIdx.y;
    const int row0 = blockIdx.x * 32;

    const float* X = (g == 0) ? queries : keys;
    const float* W = (g == 0) ? Qw : (g == 1) ? Kw : Vw;

    // load & transpose X: 32 rows x 128 k
    {
        const float4* X4 = reinterpret_cast<const float4*>(X) + row0 * 32;
        #pragma unroll
        for (int t = 0; t < 4; t++) {
            const int i = t * 256 + tid;
            const int row = i >> 5, k4 = i & 31;
            const float4 v = X4[i];
            sXT[(4 * k4 + 0) * 36 + row] = v.x;
            sXT[(4 * k4 + 1) * 36 + row] = v.y;
            sXT[(4 * k4 + 2) * 36 + row] = v.z;
            sXT[(4 * k4 + 3) * 36 + row] = v.w;
        }
    }

    // W staging indices: idx -> (colW, j); W4[colW*32 + c*8 + j] is chunk c
    const float4* W4 = reinterpret_cast<const float4*>(W);
    float4 pre[4];
    #pragma unroll
    for (int t = 0; t < 4; t++) {
        const int idx = t * 256 + tid;
        const int colW = idx >> 3, j = idx & 7;
        pre[t] = W4[colW * 32 + j];
    }

    float acc[16];
    #pragma unroll
    for (int jj = 0; jj < 16; jj++) acc[jj] = 0.0f;

    const int xbase = rg * 16;
    int buf = 0;
    for (int c = 0; c < 4; c++) {
        __syncthreads();
        #pragma unroll
        for (int t = 0; t < 4; t++) {
            const int idx = t * 256 + tid;
            const int colW = idx >> 3, j = idx & 7;
            float* d = &sW[buf][(j * 4) * 129 + colW];
            d[0 * 129] = pre[t].x;
            d[1 * 129] = pre[t].y;
            d[2 * 129] = pre[t].z;
            d[3 * 129] = pre[t].w;
        }
        __syncthreads();
        if (c < 3) {
            #pragma unroll
            for (int t = 0; t < 4; t++) {
                const int idx = t * 256 + tid;
                const int colW = idx >> 3, j = idx & 7;
                pre[t] = W4[colW * 32 + (c + 1) * 8 + j];
            }
        }
        const float* wb = sW[buf];
        #pragma unroll 8
        for (int k = 0; k < 32; k++) {
            const float w = wb[k * 129 + col];
            const int kk = c * 32 + k;
            const float4 x0 = *reinterpret_cast<const float4*>(&sXT[kk * 36 + xbase + 0]);
            const float4 x1 = *reinterpret_cast<const float4*>(&sXT[kk * 36 + xbase + 4]);
            const float4 x2 = *reinterpret_cast<const float4*>(&sXT[kk * 36 + xbase + 8]);
            const float4 x3 = *reinterpret_cast<const float4*>(&sXT[kk * 36 + xbase + 12]);
            acc[0]  += x0.x * w;  acc[1]  += x0.y * w;
            acc[2]  += x0.z * w;  acc[3]  += x0.w * w;
            acc[4]  += x1.x * w;  acc[5]  += x1.y * w;
            acc[6]  += x1.z * w;  acc[7]  += x1.w * w;
            acc[8]  += x2.x * w;  acc[9]  += x2.y * w;
            acc[10] += x2.z * w;  acc[11] += x2.w * w;
            acc[12] += x3.x * w;  acc[13] += x3.y * w;
            acc[14] += x3.z * w;  acc[15] += x3.w * w;
        }
        buf ^= 1;
    }

    if (g == 0) {
        const float b = Qb[col];
        #pragma unroll
        for (int j = 0; j < 16; j++) {
            const int row = row0 + xbase + j;
            g_Q[row * HH + col] = (acc[j] + b) * SCALE;
        }
    } else if (g == 1) {
        const float b = Kb[col];
        #pragma unroll
        for (int j = 0; j < 16; j++) {
            const int row = row0 + xbase + j;
            g_K[row * HH + col] = acc[j] + b + apK[row * HH + col];
        }
    } else {
        const float b = Vb[col];
        #pragma unroll
        for (int j = 0; j < 16; j++) {
            const int row = row0 + xbase + j;
            g_V[row * HH + col] = acc[j] + b + apV[row * HH + col];
        }
    }
}

// ---------------------------------------------------------------------------
// Base scores: g_S[b][h][l][m] = Qs[b,l,h,:] . Kc[b,m,h,:]
// grid (5 l-tiles, 32 bh), 320 threads.
// ---------------------------------------------------------------------------
__global__ __launch_bounds__(320) void qk_kernel()
{
    __shared__ float sQt[40 * 36];
    __shared__ float sKt[200 * 36];
    const int tid = threadIdx.x;
    const int bh = blockIdx.y;
    const int b = bh >> 2, h = bh & 3;
    const int l0 = blockIdx.x * 40;

    {
        const int r = tid >> 3, d4 = tid & 7;
        const float4 qv = *reinterpret_cast<const float4*>(&g_Q[(b * LL + l0 + r) * HH + h * 32 + d4 * 4]);
        *reinterpret_cast<float4*>(&sQt[r * 36 + d4 * 4]) = qv;
    }
    #pragma unroll
    for (int i = 0; i < 5; i++) {
        const int idx = i * 320 + tid;
        const int r = idx >> 3, d4 = idx & 7;
        const float4 kv = *reinterpret_cast<const float4*>(&g_K[(b * LL + r) * HH + h * 32 + d4 * 4]);
        *reinterpret_cast<float4*>(&sKt[r * 36 + d4 * 4]) = kv;
    }
    __syncthreads();

    const int ll = tid >> 3, mg = tid & 7;
    float acc[25];
    #pragma unroll
    for (int j = 0; j < 25; j++) acc[j] = 0.0f;

    #pragma unroll
    for (int d4 = 0; d4 < 8; d4++) {
        const float4 q4 = *reinterpret_cast<const float4*>(&sQt[ll * 36 + 4 * d4]);
        #pragma unroll
        for (int j = 0; j < 25; j++) {
            const float4 k4 = *reinterpret_cast<const float4*>(&sKt[(mg + 8 * j) * 36 + 4 * d4]);
            acc[j] += q4.x * k4.x + q4.y * k4.y + q4.z * k4.z + q4.w * k4.w;
        }
    }
    float* dst = &g_S[((size_t)bh * LL + l0 + ll) * LL];
    #pragma unroll
    for (int j = 0; j < 25; j++) dst[mg + 8 * j] = acc[j];
}

__device__ __forceinline__ float qdot(float4 q, float4 t) {
    return q.x * t.x + q.y * t.y + q.z * t.z + q.w * t.w;
}
__device__ __forceinline__ float dot4(float4 q, float4 a, float4 b) {
    return q.x * (a.x + b.x) + q.y * (a.y + b.y)
         + q.z * (a.z + b.z) + q.w * (a.w + b.w);
}
__device__ __forceinline__ float red8(float s) {
    s += __shfl_down_sync(0xffffffffu, s, 4);
    s += __shfl_down_sync(0xffffffffu, s, 2);
    s += __shfl_down_sync(0xffffffffu, s, 1);
    return s;
}

// ---------------------------------------------------------------------------
// Attention: one CTA per (b,l). Phase A streams ONLY tK (x6 unroll),
// base scores preloaded from g_S. Phase C = R3 config.
// ---------------------------------------------------------------------------
__global__ __launch_bounds__(256, 5) void attn_kernel(
    const float* __restrict__ tK, const float* __restrict__ tV,
    const int*   __restrict__ tmask, float* __restrict__ out)
{
    const int l = LL - 1 - blockIdx.x;
    const int b = blockIdx.y;
    const int tid  = threadIdx.x;
    const int w    = tid >> 5;
    const int lane = tid & 31;

    __shared__ float4 sQ[32];
    __shared__ float  sP[NHH * LL];
    __shared__ float4 sRed[8 * 32];

    const bool masked = (tmask[b * LL + l] != 0);

    // preload base scores
    {
        const float* Sb = &g_S[(size_t)(b * NHH) * LL * LL + (size_t)l * LL];
        for (int i = tid; i < NHH * LL; i += 256)
            sP[i] = Sb[(size_t)(i / LL) * LL * LL + (i % LL)];
    }
    if (tid < 32)
        sQ[tid] = reinterpret_cast<const float4*>(g_Q)[(b * LL + l) * 32 + tid];
    __syncthreads();

    // ---------------- Phase A: += Q . tK (tK only, x6 unroll) -------------
    if (!masked) {
        const float4* tK4 = reinterpret_cast<const float4*>(tK) + (size_t)(b * LL + l) * LL * 32 + lane;
        const float4 q = sQ[lane];
        const int head = lane >> 3;
        const bool wr = ((lane & 7) == 0);
        int m = w;
        for (; m + 40 <= l; m += 48) {
            const float4 t0 = __ldcs(tK4 + (size_t)(m)      * 32);
            const float4 t1 = __ldcs(tK4 + (size_t)(m + 8)  * 32);
            const float4 t2 = __ldcs(tK4 + (size_t)(m + 16) * 32);
            const float4 t3 = __ldcs(tK4 + (size_t)(m + 24) * 32);
            const float4 t4 = __ldcs(tK4 + (size_t)(m + 32) * 32);
            const float4 t5 = __ldcs(tK4 + (size_t)(m + 40) * 32);
            const float s0 = red8(qdot(q, t0));
            const float s1 = red8(qdot(q, t1));
            const float s2 = red8(qdot(q, t2));
            const float s3 = red8(qdot(q, t3));
            const float s4 = red8(qdot(q, t4));
            const float s5 = red8(qdot(q, t5));
            if (wr) {
                sP[head * LL + m]      += s0;
                sP[head * LL + m + 8]  += s1;
                sP[head * LL + m + 16] += s2;
                sP[head * LL + m + 24] += s3;
                sP[head * LL + m + 32] += s4;
                sP[head * LL + m + 40] += s5;
            }
        }
        for (; m <= l; m += 8) {
            const float4 t = __ldcs(tK4 + (size_t)m * 32);
            const float s = red8(qdot(q, t));
            if (wr) sP[head * LL + m] += s;
        }
    }
    __syncthreads();

    // ---------------- Phase B: softmax ----------------
    if (masked) {
        const float invL = 1.0f / (float)LL;
        for (int i = tid; i < NHH * LL; i += 256) sP[i] = invL;
    } else if (w < NHH) {
        const int h = w;
        float mx = -3.4e38f;
        for (int m = lane; m <= l; m += 32) mx = fmaxf(mx, sP[h * LL + m]);
        #pragma unroll
        for (int off = 16; off; off >>= 1)
            mx = fmaxf(mx, __shfl_xor_sync(0xffffffffu, mx, off));
        float sum = 0.0f;
        for (int m = lane; m <= l; m += 32) {
            const float e = __expf(sP[h * LL + m] - mx);
            sP[h * LL + m] = e;
            sum += e;
        }
        #pragma unroll
        for (int off = 16; off; off >>= 1)
            sum += __shfl_xor_sync(0xffffffffu, sum, off);
        const float inv = 1.0f / sum;
        for (int m = lane; m <= l; m += 32) sP[h * LL + m] *= inv;
    }
    __syncthreads();

    // ---------------- Phase C: out = sum p*(tV + V) ----------------
    {
        const int mEnd = masked ? (LL - 1) : l;
        const float4* tV4 = reinterpret_cast<const float4*>(tV) + (size_t)(b * LL + l) * LL * 32 + lane;
        const float4* V4  = reinterpret_cast<const float4*>(g_V) + (size_t)b * LL * 32 + lane;
        const int head = lane >> 3;
        float4 acc = make_float4(0.f, 0.f, 0.f, 0.f);
        int m = w;
        for (; m + 24 <= mEnd; m += 32) {
            const float p0 = sP[head * LL + m];
            const float p1 = sP[head * LL + m + 8];
            const float p2 = sP[head * LL + m + 16];
            const float p3 = sP[head * LL + m + 24];
            const float4 t0 = __ldcs(tV4 + (size_t)(m)      * 32);
            const float4 t1 = __ldcs(tV4 + (size_t)(m + 8)  * 32);
            const float4 t2 = __ldcs(tV4 + (size_t)(m + 16) * 32);
            const float4 t3 = __ldcs(tV4 + (size_t)(m + 24) * 32);
            const float4 v0 = V4[(m)      * 32];
            const float4 v1 = V4[(m + 8)  * 32];
            const float4 v2 = V4[(m + 16) * 32];
            const float4 v3 = V4[(m + 24) * 32];
            acc.x += p0 * (t0.x + v0.x) + p1 * (t1.x + v1.x)
                   + p2 * (t2.x + v2.x) + p3 * (t3.x + v3.x);
            acc.y += p0 * (t0.y + v0.y) + p1 * (t1.y + v1.y)
                   + p2 * (t2.y + v2.y) + p3 * (t3.y + v3.y);
            acc.z += p0 * (t0.z + v0.z) + p1 * (t1.z + v1.z)
                   + p2 * (t2.z + v2.z) + p3 * (t3.z + v3.z);
            acc.w += p0 * (t0.w + v0.w) + p1 * (t1.w + v1.w)
                   + p2 * (t2.w + v2.w) + p3 * (t3.w + v3.w);
        }
        for (; m <= mEnd; m += 8) {
            const float p = sP[head * LL + m];
            const float4 t = __ldcs(tV4 + (size_t)m * 32);
            const float4 v = V4[m * 32];
            acc.x += p * (t.x + v.x);
            acc.y += p * (t.y + v.y);
            acc.z += p * (t.z + v.z);
            acc.w += p * (t.w + v.w);
        }
        sRed[w * 32 + lane] = acc;
    }
    __syncthreads();

    if (tid < 32) {
        float4 r = sRed[tid];
        #pragma unroll
        for (int w2 = 1; w2 < 8; w2++) {
            const float4 a = sRed[w2 * 32 + tid];
            r.x += a.x; r.y += a.y; r.z += a.z; r.w += a.w;
        }
        reinterpret_cast<float4*>(out)[(b * LL + l) * 32 + tid] = r;
    }
}

extern "C" void kernel_launch(void* const* d_in, const int* in_sizes, int n_in,
                              void* d_out, int out_size)
{
    const float* queries = (const float*)d_in[0];
    const float* keys    = (const float*)d_in[1];
    const int*   tmask   = (const int*)  d_in[2];
    // d_in[3] = attn_mask (causal triu, analytic -> unused)
    const float* tK      = (const float*)d_in[4];
    const float* tV      = (const float*)d_in[5];
    const float* apK     = (const float*)d_in[6];
    const float* apV     = (const float*)d_in[7];
    const float* Qw      = (const float*)d_in[8];
    const float* Qb      = (const float*)d_in[9];
    const float* Kw      = (const float*)d_in[10];
    const float* Kb      = (const float*)d_in[11];
    const float* Vw      = (const float*)d_in[12];
    const float* Vb      = (const float*)d_in[13];
    float* out = (float*)d_out;

    proj_kernel<<<dim3(50, 3), 256>>>(queries, keys, apK, apV, Qw, Kw, Vw, Qb, Kb, Vb);
    qk_kernel<<<dim3(5, 32), 320>>>();
    dim3 grid(LL, BB);
    attn_kernel<<<grid, 256>>>(tK, tV, tmask, out);
}

// round 8
// speedup vs baseline: 1.1958x; 1.1958x over previous
#include <cuda_runtime.h>
#include <cuda_bf16.h>

#define BB 8
#define LL 200
#define HH 128
#define NHH 4
#define DHH 32
#define SCALE 0.17677669529663688f   // 1/sqrt(32)

__device__ float g_Q[BB * LL * HH];
__device__ float g_K[BB * LL * HH];
__device__ float g_V[BB * LL * HH];

// ---------------------------------------------------------------------------
// Projection: grid (50 row-tiles, 3 matrices) = 150 CTAs (~one wave), 256 thr.
// W staged VERBATIM (no transpose) into smem padded to 65 floats/row:
// bank(col*65+k) = (col+k)%32 -> conflict-free scalar reads for fixed k.
// k staged in two 64-wide halves (33KB sW + 18KB sXT = 51KB).
// ---------------------------------------------------------------------------
__global__ __launch_bounds__(256) void proj_kernel(
    const float* __restrict__ queries, const float* __restrict__ keys,
    const float* __restrict__ apK, const float* __restrict__ apV,
    const float* __restrict__ Qw, const float* __restrict__ Kw,
    const float* __restrict__ Vw,
    const float* __restrict__ Qb, const float* __restrict__ Kb,
    const float* __restrict__ Vb)
{
    __shared__ float sXT[HH * 36];      // [k][row(+pad)]  18 KB
    __shared__ float sW[HH * 65];       // [col][k-half(+pad)]  33 KB

    const int tid = threadIdx.x;
    const int col = tid & 127;
    const int rg  = tid >> 7;
    const int g   = blockIdx.y;
    const int row0 = blockIdx.x * 32;

    const float* X = (g == 0) ? queries : keys;
    const float* W = (g == 0) ? Qw : (g == 1) ? Kw : Vw;
    const float4* W4 = reinterpret_cast<const float4*>(W);

    // load & transpose X: 32 rows x 128 k
    {
        const float4* X4 = reinterpret_cast<const float4*>(X) + row0 * 32;
        #pragma unroll
        for (int t = 0; t < 4; t++) {
            const int i = t * 256 + tid;
            const int row = i >> 5, k4 = i & 31;
            const float4 v = X4[i];
            sXT[(4 * k4 + 0) * 36 + row] = v.x;
            sXT[(4 * k4 + 1) * 36 + row] = v.y;
            sXT[(4 * k4 + 2) * 36 + row] = v.z;
            sXT[(4 * k4 + 3) * 36 + row] = v.w;
        }
    }

    float acc[16];
    #pragma unroll
    for (int j = 0; j < 16; j++) acc[j] = 0.0f;

    const int xbase = rg * 16;

    #pragma unroll
    for (int half = 0; half < 2; half++) {
        __syncthreads();
        // stage W[:, half*64 : half*64+64] verbatim (coalesced float4 loads)
        #pragma unroll
        for (int t = 0; t < 8; t++) {
            const int idx = t * 256 + tid;          // 0..2047
            const int cw = idx >> 4, k4 = idx & 15; // 16 float4 per col-half
            const float4 v = W4[cw * 32 + half * 16 + k4];
            float* d = &sW[cw * 65 + k4 * 4];
            d[0] = v.x; d[1] = v.y; d[2] = v.z; d[3] = v.w;
        }
        __syncthreads();

        const float* wp = &sW[col * 65];
        #pragma unroll 8
        for (int k = 0; k < 64; k++) {
            const float w = wp[k];
            const int kk = half * 64 + k;
            const float4 x0 = *reinterpret_cast<const float4*>(&sXT[kk * 36 + xbase + 0]);
            const float4 x1 = *reinterpret_cast<const float4*>(&sXT[kk * 36 + xbase + 4]);
            const float4 x2 = *reinterpret_cast<const float4*>(&sXT[kk * 36 + xbase + 8]);
            const float4 x3 = *reinterpret_cast<const float4*>(&sXT[kk * 36 + xbase + 12]);
            acc[0]  += x0.x * w;  acc[1]  += x0.y * w;
            acc[2]  += x0.z * w;  acc[3]  += x0.w * w;
            acc[4]  += x1.x * w;  acc[5]  += x1.y * w;
            acc[6]  += x1.z * w;  acc[7]  += x1.w * w;
            acc[8]  += x2.x * w;  acc[9]  += x2.y * w;
            acc[10] += x2.z * w;  acc[11] += x2.w * w;
            acc[12] += x3.x * w;  acc[13] += x3.y * w;
            acc[14] += x3.z * w;  acc[15] += x3.w * w;
        }
    }

    if (g == 0) {
        const float b = Qb[col];
        #pragma unroll
        for (int j = 0; j < 16; j++) {
            const int row = row0 + xbase + j;
            g_Q[row * HH + col] = (acc[j] + b) * SCALE;
        }
    } else if (g == 1) {
        const float b = Kb[col];
        #pragma unroll
        for (int j = 0; j < 16; j++) {
            const int row = row0 + xbase + j;
            g_K[row * HH + col] = acc[j] + b + apK[row * HH + col];
        }
    } else {
        const float b = Vb[col];
        #pragma unroll
        for (int j = 0; j < 16; j++) {
            const int row = row0 + xbase + j;
            g_V[row * HH + col] = acc[j] + b + apV[row * HH + col];
        }
    }
}

__device__ __forceinline__ float dot4(float4 q, float4 a, float4 b) {
    return q.x * (a.x + b.x) + q.y * (a.y + b.y)
         + q.z * (a.z + b.z) + q.w * (a.w + b.w);
}
__device__ __forceinline__ float red8(float s) {
    s += __shfl_down_sync(0xffffffffu, s, 4);
    s += __shfl_down_sync(0xffffffffu, s, 2);
    s += __shfl_down_sync(0xffffffffu, s, 1);
    return s;
}

// ---------------------------------------------------------------------------
// Attention (R6/R3 configuration, measured 36.7us): one CTA per (b,l).
// 256 threads, x4 m-unroll, min 5 CTAs/SM.
// ---------------------------------------------------------------------------
__global__ __launch_bounds__(256, 5) void attn_kernel(
    const float* __restrict__ tK, const float* __restrict__ tV,
    const int*   __restrict__ tmask, float* __restrict__ out)
{
    const int l = LL - 1 - blockIdx.x;   // heaviest rows first
    const int b = blockIdx.y;
    const int tid  = threadIdx.x;
    const int w    = tid >> 5;
    const int lane = tid & 31;

    __shared__ float4 sQ[32];
    __shared__ float  sP[NHH * LL];
    __shared__ float4 sRed[8 * 32];

    const bool masked = (tmask[b * LL + l] != 0);

    if (tid < 32)
        sQ[tid] = reinterpret_cast<const float4*>(g_Q)[(b * LL + l) * 32 + tid];
    __syncthreads();

    // ---------------- Phase A: logits ----------------
    if (!masked) {
        const float4* tK4 = reinterpret_cast<const float4*>(tK) + (size_t)(b * LL + l) * LL * 32 + lane;
        const float4* K4  = reinterpret_cast<const float4*>(g_K) + (size_t)b * LL * 32 + lane;
        const float4 q = sQ[lane];
        const int head = lane >> 3;
        const bool wr = ((lane & 7) == 0);
        int m = w;
        for (; m + 24 <= l; m += 32) {
            const float4 t0 = __ldcs(tK4 + (size_t)(m)      * 32);
            const float4 t1 = __ldcs(tK4 + (size_t)(m + 8)  * 32);
            const float4 t2 = __ldcs(tK4 + (size_t)(m + 16) * 32);
            const float4 t3 = __ldcs(tK4 + (size_t)(m + 24) * 32);
            const float4 k0 = K4[(m)      * 32];
            const float4 k1 = K4[(m + 8)  * 32];
            const float4 k2 = K4[(m + 16) * 32];
            const float4 k3 = K4[(m + 24) * 32];
            float s0 = red8(dot4(q, t0, k0));
            float s1 = red8(dot4(q, t1, k1));
            float s2 = red8(dot4(q, t2, k2));
            float s3 = red8(dot4(q, t3, k3));
            if (wr) {
                sP[head * LL + m]      = s0;
                sP[head * LL + m + 8]  = s1;
                sP[head * LL + m + 16] = s2;
                sP[head * LL + m + 24] = s3;
            }
        }
        for (; m <= l; m += 8) {
            const float4 t = __ldcs(tK4 + (size_t)m * 32);
            const float4 k = K4[m * 32];
            const float s = red8(dot4(q, t, k));
            if (wr) sP[head * LL + m] = s;
        }
    }
    __syncthreads();

    // ---------------- Phase B: softmax ----------------
    if (masked) {
        const float invL = 1.0f / (float)LL;
        for (int i = tid; i < NHH * LL; i += 256) sP[i] = invL;
    } else if (w < NHH) {
        const int h = w;
        float mx = -3.4e38f;
        for (int m = lane; m <= l; m += 32) mx = fmaxf(mx, sP[h * LL + m]);
        #pragma unroll
        for (int off = 16; off; off >>= 1)
            mx = fmaxf(mx, __shfl_xor_sync(0xffffffffu, mx, off));
        float sum = 0.0f;
        for (int m = lane; m <= l; m += 32) {
            const float e = __expf(sP[h * LL + m] - mx);
            sP[h * LL + m] = e;
            sum += e;
        }
        #pragma unroll
        for (int off = 16; off; off >>= 1)
            sum += __shfl_xor_sync(0xffffffffu, sum, off);
        const float inv = 1.0f / sum;
        for (int m = lane; m <= l; m += 32) sP[h * LL + m] *= inv;
    }
    __syncthreads();

    // ---------------- Phase C: output ----------------
    {
        const int mEnd = masked ? (LL - 1) : l;
        const float4* tV4 = reinterpret_cast<const float4*>(tV) + (size_t)(b * LL + l) * LL * 32 + lane;
        const float4* V4  = reinterpret_cast<const float4*>(g_V) + (size_t)b * LL * 32 + lane;
        const int head = lane >> 3;
        float4 acc = make_float4(0.f, 0.f, 0.f, 0.f);
        int m = w;
        for (; m + 24 <= mEnd; m += 32) {
            const float p0 = sP[head * LL + m];
            const float p1 = sP[head * LL + m + 8];
            const float p2 = sP[head * LL + m + 16];
            const float p3 = sP[head * LL + m + 24];
            const float4 t0 = __ldcs(tV4 + (size_t)(m)      * 32);
            const float4 t1 = __ldcs(tV4 + (size_t)(m + 8)  * 32);
            const float4 t2 = __ldcs(tV4 + (size_t)(m + 16) * 32);
            const float4 t3 = __ldcs(tV4 + (size_t)(m + 24) * 32);
            const float4 v0 = V4[(m)      * 32];
            const float4 v1 = V4[(m + 8)  * 32];
            const float4 v2 = V4[(m + 16) * 32];
            const float4 v3 = V4[(m + 24) * 32];
            acc.x += p0 * (t0.x + v0.x) + p1 * (t1.x + v1.x)
                   + p2 * (t2.x + v2.x) + p3 * (t3.x + v3.x);
            acc.y += p0 * (t0.y + v0.y) + p1 * (t1.y + v1.y)
                   + p2 * (t2.y + v2.y) + p3 * (t3.y + v3.y);
            acc.z += p0 * (t0.z + v0.z) + p1 * (t1.z + v1.z)
                   + p2 * (t2.z + v2.z) + p3 * (t3.z + v3.z);
            acc.w += p0 * (t0.w + v0.w) + p1 * (t1.w + v1.w)
                   + p2 * (t2.w + v2.w) + p3 * (t3.w + v3.w);
        }
        for (; m <= mEnd; m += 8) {
            const float p = sP[head * LL + m];
            const float4 t = __ldcs(tV4 + (size_t)m * 32);
            const float4 v = V4[m * 32];
            acc.x += p * (t.x + v.x);
            acc.y += p * (t.y + v.y);
            acc.z += p * (t.z + v.z);
            acc.w += p * (t.w + v.w);
        }
        sRed[w * 32 + lane] = acc;
    }
    __syncthreads();

    if (tid < 32) {
        float4 r = sRed[tid];
        #pragma unroll
        for (int w2 = 1; w2 < 8; w2++) {
            const float4 a = sRed[w2 * 32 + tid];
            r.x += a.x; r.y += a.y; r.z += a.z; r.w += a.w;
        }
        reinterpret_cast<float4*>(out)[(b * LL + l) * 32 + tid] = r;
    }
}

extern "C" void kernel_launch(void* const* d_in, const int* in_sizes, int n_in,
                              void* d_out, int out_size)
{
    const float* queries = (const float*)d_in[0];
    const float* keys    = (const float*)d_in[1];
    const int*   tmask   = (const int*)  d_in[2];
    // d_in[3] = attn_mask (causal triu, analytic -> unused)
    const float* tK      = (const float*)d_in[4];
    const float* tV      = (const float*)d_in[5];
    const float* apK     = (const float*)d_in[6];
    const float* apV     = (const float*)d_in[7];
    const float* Qw      = (const float*)d_in[8];
    const float* Qb      = (const float*)d_in[9];
    const float* Kw      = (const float*)d_in[10];
    const float* Kb      = (const float*)d_in[11];
    const float* Vw      = (const float*)d_in[12];
    const float* Vb      = (const float*)d_in[13];
    float* out = (float*)d_out;

    proj_kernel<<<dim3(50, 3), 256>>>(queries, keys, apK, apV, Qw, Kw, Vw, Qb, Kb, Vb);
    dim3 grid(LL, BB);
    attn_kernel<<<grid, 256>>>(tK, tV, tmask, out);
}